// round 4
// baseline (speedup 1.0000x reference)
#include <cuda_runtime.h>
#include <cstdint>

// ---------------------------------------------------------------------------
// ShapletLearner via warp-level tf32 mma.sync (m16n8k8) with hi/lo split:
//   cross[s,l] = Hankel(ts) @ shapelets^T  done as hi*hi + hi*lo + lo*hi
//   dist = (wsq[s] - 2*cross + ssq[l]) / K ; d[l] = min_s ; out = d@W^T + b
// One CTA (128 thr, 4 warps) per batch row. Warps split N (16 l-cols each).
// A fragments come from a 12-slot circular register buffer exploiting the
// Hankel structure: only 4 new LDS per operand per 16-row M tile.
// ---------------------------------------------------------------------------

constexpr int Bc = 2048;
constexpr int Qc = 1024;
constexpr int Kc = 32;
constexpr int Lc = 64;
constexpr int Sc = Qc - Kc + 1;   // 993

static __device__ __forceinline__ uint32_t to_tf32(float x) {
    uint32_t v;
    asm("cvt.rna.tf32.f32 %0, %1;" : "=r"(v) : "f"(x));
    return v;
}

// D += A(tf32) * B(tf32), m16n8k8
#define MMA(d0,d1,d2,d3, a0,a1,a2,a3, b0,b1) \
    asm("mma.sync.aligned.m16n8k8.row.col.f32.tf32.tf32.f32 " \
        "{%0,%1,%2,%3}, {%4,%5,%6,%7}, {%8,%9}, {%0,%1,%2,%3};" \
        : "+f"(d0), "+f"(d1), "+f"(d2), "+f"(d3) \
        : "r"(a0), "r"(a1), "r"(a2), "r"(a3), "r"(b0), "r"(b1))

// one k-step (k8) for both n-tiles, 3-pass hi/lo compensation (6 MMAs)
#define KSTEP(O, KT) do { \
    enum { J0 = (O + 2*KT) % 12, J1 = (O + 2*KT + 2) % 12, \
           J2 = (O + 2*KT + 1) % 12, J3 = (O + 2*KT + 3) % 12 }; \
    MMA(d00,d01,d02,d03, vh[J0],vh[J1],vh[J2],vh[J3], bh[0][KT][0], bh[0][KT][1]); \
    MMA(d00,d01,d02,d03, vh[J0],vh[J1],vh[J2],vh[J3], bl[0][KT][0], bl[0][KT][1]); \
    MMA(d00,d01,d02,d03, vl[J0],vl[J1],vl[J2],vl[J3], bh[0][KT][0], bh[0][KT][1]); \
    MMA(d10,d11,d12,d13, vh[J0],vh[J1],vh[J2],vh[J3], bh[1][KT][0], bh[1][KT][1]); \
    MMA(d10,d11,d12,d13, vh[J0],vh[J1],vh[J2],vh[J3], bl[1][KT][0], bl[1][KT][1]); \
    MMA(d10,d11,d12,d13, vl[J0],vl[J1],vl[J2],vl[J3], bh[1][KT][0], bh[1][KT][1]); \
} while (0)

// one m16 tile at ring offset O, tile index TT (s0 = 16*TT)
#define TILE(O, TT) do { \
    const int s0_ = (TT) << 4; \
    const float wq0_ = wsq_sh[s0_ + nrow]; \
    const float wq1_ = wsq_sh[s0_ + nrow + 8]; \
    float d00=0.f,d01=0.f,d02=0.f,d03=0.f,d10=0.f,d11=0.f,d12=0.f,d13=0.f; \
    KSTEP(O, 0); KSTEP(O, 1); KSTEP(O, 2); KSTEP(O, 3); \
    mn00 = fminf(mn00, fmaf(d00, -2.f, wq0_)); \
    mn01 = fminf(mn01, fmaf(d01, -2.f, wq0_)); \
    mn02 = fminf(mn02, fmaf(d02, -2.f, wq1_)); \
    mn03 = fminf(mn03, fmaf(d03, -2.f, wq1_)); \
    mn10 = fminf(mn10, fmaf(d10, -2.f, wq0_)); \
    mn11 = fminf(mn11, fmaf(d11, -2.f, wq0_)); \
    mn12 = fminf(mn12, fmaf(d12, -2.f, wq1_)); \
    mn13 = fminf(mn13, fmaf(d13, -2.f, wq1_)); \
    { enum { L0 = (O+10)%12, L1 = (O+11)%12, L2 = (O+12)%12, L3 = (O+13)%12 }; \
      const int gi_ = s0_ + tbase + 40; \
      vh[L0] = ts_hi[gi_];      vl[L0] = ts_lo[gi_]; \
      vh[L1] = ts_hi[gi_ + 4];  vl[L1] = ts_lo[gi_ + 4]; \
      vh[L2] = ts_hi[gi_ + 8];  vl[L2] = ts_lo[gi_ + 8]; \
      vh[L3] = ts_hi[gi_ + 12]; vl[L3] = ts_lo[gi_ + 12]; } \
} while (0)

__global__ __launch_bounds__(128) void shapelet_mma(
    const float* __restrict__ ts,        // [B, Q]
    const float* __restrict__ shp,       // [L, K]
    const float* __restrict__ fc_w,      // [2, L]
    const float* __restrict__ fc_b,      // [2]
    float* __restrict__ out)             // [B, 2]
{
    __shared__ __align__(16) float    ts_sh[1120];   // raw fp32 (zero-padded)
    __shared__ __align__(16) uint32_t ts_hi[1120];   // tf32(x)
    __shared__ __align__(16) uint32_t ts_lo[1120];   // tf32(x - hi)
    __shared__ float wsq_sh[1056];                   // 1e38 for s >= Sc
    __shared__ float ssq_sh[Lc];                     // raw sum shp^2
    __shared__ float dsh[Lc];

    const int b    = blockIdx.x;
    const int tid  = threadIdx.x;
    const int w    = tid >> 5;
    const int lane = tid & 31;
    const int nrow = lane >> 2;   // fragment row group / B n-offset
    const int kq   = lane & 3;    // fragment col group

    // ---- stage ts (coalesced float4) + zero pad to 1120 ----
    {
        const float4* src = reinterpret_cast<const float4*>(ts + (size_t)b * Qc);
        float4* dst = reinterpret_cast<float4*>(ts_sh);
        dst[tid]       = src[tid];
        dst[128 + tid] = src[128 + tid];
        if (tid < 24) dst[256 + tid] = make_float4(0.f, 0.f, 0.f, 0.f);
    }
    __syncthreads();

    // ---- hi/lo split of ts ----
    #pragma unroll
    for (int i = tid; i < 1120; i += 128) {
        const float x = ts_sh[i];
        const uint32_t h = to_tf32(x);
        ts_hi[i] = h;
        ts_lo[i] = to_tf32(x - __uint_as_float(h));
    }

    // ---- wsq[s] (exact fp32), 9 windows per thread, incremental ----
    {
        const int sbase = tid * 9;
        if (sbase < 1056) {
            float ww = 0.f;
            #pragma unroll
            for (int k = 0; k < Kc; k++) {
                const float x = ts_sh[sbase + k];
                ww = fmaf(x, x, ww);
            }
            wsq_sh[sbase] = (sbase < Sc) ? ww : 1e38f;
            #pragma unroll
            for (int i = 1; i < 9; i++) {
                const int s = sbase + i;
                const float xo = ts_sh[s - 1], xn = ts_sh[s + 31];
                ww = ww - xo * xo + xn * xn;
                if (s < 1056) wsq_sh[s] = (s < Sc) ? ww : 1e38f;
            }
        }
    }

    // ---- ssq[l] raw (exact fp32) ----
    if (tid < Lc) {
        float s = 0.f;
        #pragma unroll
        for (int k = 0; k < Kc; k++) {
            const float v = shp[tid * Kc + k];
            s = fmaf(v, v, s);
        }
        ssq_sh[tid] = s;
    }

    // ---- B fragments in registers (hi/lo), warp covers n = w*16..w*16+15 ----
    uint32_t bh[2][4][2], bl[2][4][2];
    #pragma unroll
    for (int nt = 0; nt < 2; nt++)
        #pragma unroll
        for (int kt = 0; kt < 4; kt++)
            #pragma unroll
            for (int j = 0; j < 2; j++) {
                const int n = w * 16 + nt * 8 + nrow;
                const int k = kq + 4 * j + 8 * kt;
                const float x = shp[n * Kc + k];
                const uint32_t h = to_tf32(x);
                bh[nt][kt][j] = h;
                bl[nt][kt][j] = to_tf32(x - __uint_as_float(h));
            }
    __syncthreads();

    // ---- main loop: 66 m16 tiles, ring buffer of A values ----
    float mn00 = 3.4e38f, mn01 = 3.4e38f, mn02 = 3.4e38f, mn03 = 3.4e38f;
    float mn10 = 3.4e38f, mn11 = 3.4e38f, mn12 = 3.4e38f, mn13 = 3.4e38f;

    uint32_t vh[12], vl[12];
    const int tbase = nrow + kq;   // r + c0 in [0,10]
    #pragma unroll
    for (int j = 0; j < 10; j++) {
        vh[j] = ts_hi[tbase + 4 * j];
        vl[j] = ts_lo[tbase + 4 * j];
    }

    #pragma unroll 1
    for (int it = 0; it < 22; it++) {
        const int t3 = it * 3;
        TILE(0, t3);
        TILE(4, t3 + 1);
        TILE(8, t3 + 2);
    }

    // ---- reduce: rows within thread, then across row groups via shfl ----
    float m0 = fminf(mn00, mn02);   // col = 2*kq   (nt 0)
    float m1 = fminf(mn01, mn03);   // col = 2*kq+1 (nt 0)
    float m2 = fminf(mn10, mn12);   // nt 1
    float m3 = fminf(mn11, mn13);
    #pragma unroll
    for (int off = 4; off < 32; off <<= 1) {
        m0 = fminf(m0, __shfl_xor_sync(0xffffffffu, m0, off));
        m1 = fminf(m1, __shfl_xor_sync(0xffffffffu, m1, off));
        m2 = fminf(m2, __shfl_xor_sync(0xffffffffu, m2, off));
        m3 = fminf(m3, __shfl_xor_sync(0xffffffffu, m3, off));
    }
    if (nrow == 0) {
        const int n0 = w * 16 + 2 * kq;
        dsh[n0]     = (m0 + ssq_sh[n0])     * (1.0f / Kc);
        dsh[n0 + 1] = (m1 + ssq_sh[n0 + 1]) * (1.0f / Kc);
        dsh[n0 + 8] = (m2 + ssq_sh[n0 + 8]) * (1.0f / Kc);
        dsh[n0 + 9] = (m3 + ssq_sh[n0 + 9]) * (1.0f / Kc);
    }
    __syncthreads();

    // ---- FC epilogue: warp 0 -> class 0, warp 1 -> class 1 ----
    if (tid < 2 * 32) {
        const int c = tid >> 5;
        const int l = tid & 31;
        float p = dsh[l] * fc_w[c * Lc + l]
                + dsh[l + 32] * fc_w[c * Lc + l + 32];
        #pragma unroll
        for (int off = 16; off > 0; off >>= 1)
            p += __shfl_down_sync(0xffffffffu, p, off);
        if (l == 0) out[b * 2 + c] = p + fc_b[c];
    }
}

extern "C" void kernel_launch(void* const* d_in, const int* in_sizes, int n_in,
                              void* d_out, int out_size)
{
    (void)in_sizes; (void)n_in; (void)out_size;
    const float* ts   = (const float*)d_in[0];
    const float* shp  = (const float*)d_in[1];
    const float* fc_w = (const float*)d_in[2];
    const float* fc_b = (const float*)d_in[3];
    float* out        = (float*)d_out;
    shapelet_mma<<<Bc, 128>>>(ts, shp, fc_w, fc_b, out);
}

// round 5
// speedup vs baseline: 2.5301x; 2.5301x over previous
#include <cuda_runtime.h>
#include <cuda_bf16.h>
#include <cstdint>

// ---------------------------------------------------------------------------
// ShapletLearner via bf16 mma.sync m16n8k16, 2-term split (hi+lo), 3 passes:
//   cross = Hankel(ts) @ shp^T  ~=  ah*bh + ah*bl + al*bh   (drop al*bl ~2^-18)
//   dist = (wsq[s] - 2*cross + ssq[l])/K ; d[l]=min_s ; out = d@W^T + b
// One CTA (128 thr / 4 warps) per batch row; warps split N (16 l-cols each).
// Hankel trick: A-fragment packed pairs depend only on (s0 + r + c); per m16
// tile only pairs at base+8u, u=0..4 are needed, and a1==a2 -> 6-slot ring,
// 2 new LDS per split per tile. 12 HMMA per tile (was 24 tf32 in R4).
// ---------------------------------------------------------------------------

constexpr int Bc = 2048;
constexpr int Qc = 1024;
constexpr int Kc = 32;
constexpr int Lc = 64;
constexpr int Sc = Qc - Kc + 1;   // 993

// D += A(bf16) * B(bf16), m16n8k16
#define MMAB(d0,d1,d2,d3, a0,a1,a2,a3, b0,b1) \
    asm("mma.sync.aligned.m16n8k16.row.col.f32.bf16.bf16.f32 " \
        "{%0,%1,%2,%3}, {%4,%5,%6,%7}, {%8,%9}, {%0,%1,%2,%3};" \
        : "+f"(d0), "+f"(d1), "+f"(d2), "+f"(d3) \
        : "r"(a0), "r"(a1), "r"(a2), "r"(a3), "r"(b0), "r"(b1))

// one k16 chunk KC for both n-tiles; ring offset O (= (2t)%6, compile-time)
#define KCH(O, KC) do { \
    enum { I0 = ((O) + 2*(KC)) % 6, I1 = ((O) + 2*(KC) + 1) % 6, \
           I2 = ((O) + 2*(KC) + 2) % 6 }; \
    MMAB(d00,d01,d02,d03, rh[I0],rh[I1],rh[I1],rh[I2], Bh[0][KC][0], Bh[0][KC][1]); \
    MMAB(d00,d01,d02,d03, rh[I0],rh[I1],rh[I1],rh[I2], Bl[0][KC][0], Bl[0][KC][1]); \
    MMAB(d00,d01,d02,d03, rl[I0],rl[I1],rl[I1],rl[I2], Bh[0][KC][0], Bh[0][KC][1]); \
    MMAB(d10,d11,d12,d13, rh[I0],rh[I1],rh[I1],rh[I2], Bh[1][KC][0], Bh[1][KC][1]); \
    MMAB(d10,d11,d12,d13, rh[I0],rh[I1],rh[I1],rh[I2], Bl[1][KC][0], Bl[1][KC][1]); \
    MMAB(d10,d11,d12,d13, rl[I0],rl[I1],rl[I1],rl[I2], Bh[1][KC][0], Bh[1][KC][1]); \
} while (0)

// one m16 tile: ring offset O = (2*TT)%6 (compile-time), tile index TT
#define TILE(O, TT) do { \
    const int s0_ = (TT) << 4; \
    const float wq0_ = wsq_sh[s0_ + nrow]; \
    const float wq1_ = wsq_sh[s0_ + nrow + 8]; \
    float d00=0.f,d01=0.f,d02=0.f,d03=0.f,d10=0.f,d11=0.f,d12=0.f,d13=0.f; \
    KCH(O, 0); KCH(O, 1); \
    mn00 = fminf(mn00, fmaf(d00, -2.f, wq0_)); \
    mn01 = fminf(mn01, fmaf(d01, -2.f, wq0_)); \
    mn02 = fminf(mn02, fmaf(d02, -2.f, wq1_)); \
    mn03 = fminf(mn03, fmaf(d03, -2.f, wq1_)); \
    mn10 = fminf(mn10, fmaf(d10, -2.f, wq0_)); \
    mn11 = fminf(mn11, fmaf(d11, -2.f, wq0_)); \
    mn12 = fminf(mn12, fmaf(d12, -2.f, wq1_)); \
    mn13 = fminf(mn13, fmaf(d13, -2.f, wq1_)); \
    { enum { S5 = ((O) + 5) % 6, S6 = (O) % 6 };  /* m=2t+5, m=2t+6 */ \
      const int gi_ = s0_ + tb; \
      rh[S5] = pair_hi[gi_ + 40];  rl[S5] = pair_lo[gi_ + 40]; \
      rh[S6] = pair_hi[gi_ + 48];  rl[S6] = pair_lo[gi_ + 48]; } \
} while (0)

static __device__ __forceinline__ uint32_t pack_bf16x2(float lo, float hi) {
    uint32_t r;
    asm("cvt.rn.bf16x2.f32 %0, %1, %2;" : "=r"(r) : "f"(hi), "f"(lo));
    return r;
}

__global__ __launch_bounds__(128) void shapelet_bmma(
    const float* __restrict__ ts,        // [B, Q]
    const float* __restrict__ shp,       // [L, K]
    const float* __restrict__ fc_w,      // [2, L]
    const float* __restrict__ fc_b,      // [2]
    float* __restrict__ out)             // [B, 2]
{
    __shared__ __align__(16) float    ts_sh[1152];    // fp32, zero-padded
    __shared__ __align__(16) uint32_t pair_hi[1120];  // (bf16 ts[i], bf16 ts[i+1])
    __shared__ __align__(16) uint32_t pair_lo[1120];  // residual pairs
    __shared__ float wsq_sh[1056];                    // 1e38 guard for s >= Sc
    __shared__ float ssq_sh[Lc];
    __shared__ float dsh[Lc];

    const int b    = blockIdx.x;
    const int tid  = threadIdx.x;
    const int w    = tid >> 5;
    const int lane = tid & 31;
    const int nrow = lane >> 2;   // fragment row group / B n-offset
    const int kq   = lane & 3;    // fragment col group

    // ---- stage ts + zero pad to 1152 ----
    {
        const float4* src = reinterpret_cast<const float4*>(ts + (size_t)b * Qc);
        float4* dst = reinterpret_cast<float4*>(ts_sh);
        dst[tid]       = src[tid];
        dst[128 + tid] = src[128 + tid];
        if (tid < 32) dst[256 + tid] = make_float4(0.f, 0.f, 0.f, 0.f);
    }
    __syncthreads();

    // ---- build packed bf16 hi/lo pair arrays ----
    #pragma unroll
    for (int i = tid; i < 1120; i += 128) {
        const float x0 = ts_sh[i], x1 = ts_sh[i + 1];
        const __nv_bfloat16 h0 = __float2bfloat16_rn(x0);
        const __nv_bfloat16 h1 = __float2bfloat16_rn(x1);
        pair_hi[i] = (uint32_t)__bfloat16_as_ushort(h0)
                   | ((uint32_t)__bfloat16_as_ushort(h1) << 16);
        pair_lo[i] = pack_bf16x2(x0 - __bfloat162float(h0),
                                 x1 - __bfloat162float(h1));
    }

    // ---- wsq[s] exact fp32, incremental, 9 windows per thread ----
    {
        const int sbase = tid * 9;
        if (sbase < 1056) {
            float ww = 0.f;
            #pragma unroll
            for (int k = 0; k < Kc; k++) {
                const float x = ts_sh[sbase + k];
                ww = fmaf(x, x, ww);
            }
            wsq_sh[sbase] = (sbase < Sc) ? ww : 1e38f;
            #pragma unroll
            for (int i = 1; i < 9; i++) {
                const int s = sbase + i;
                const float xo = ts_sh[s - 1], xn = ts_sh[s + 31];
                ww = ww - xo * xo + xn * xn;
                if (s < 1056) wsq_sh[s] = (s < Sc) ? ww : 1e38f;
            }
        }
    }

    // ---- ssq[l] exact fp32 ----
    if (tid < Lc) {
        float s = 0.f;
        #pragma unroll
        for (int k = 0; k < Kc; k++) {
            const float v = shp[tid * Kc + k];
            s = fmaf(v, v, s);
        }
        ssq_sh[tid] = s;
    }

    // ---- B fragments (hi/lo): warp covers n = w*16 .. w*16+15 ----
    // Bx[nt][kc][j]: n = w*16 + nt*8 + nrow, k = 16*kc + 8*j + 2*kq + {0,1}
    uint32_t Bh[2][2][2], Bl[2][2][2];
    #pragma unroll
    for (int nt = 0; nt < 2; nt++)
        #pragma unroll
        for (int kc = 0; kc < 2; kc++)
            #pragma unroll
            for (int j = 0; j < 2; j++) {
                const int n = w * 16 + nt * 8 + nrow;
                const int k = 16 * kc + 8 * j + 2 * kq;
                const float x0 = shp[n * Kc + k];
                const float x1 = shp[n * Kc + k + 1];
                const __nv_bfloat16 h0 = __float2bfloat16_rn(x0);
                const __nv_bfloat16 h1 = __float2bfloat16_rn(x1);
                Bh[nt][kc][j] = (uint32_t)__bfloat16_as_ushort(h0)
                              | ((uint32_t)__bfloat16_as_ushort(h1) << 16);
                Bl[nt][kc][j] = pack_bf16x2(x0 - __bfloat162float(h0),
                                            x1 - __bfloat162float(h1));
            }
    __syncthreads();

    // ---- main loop: 66 m16 tiles, 6-slot pair ring ----
    float mn00 = 3.4e38f, mn01 = 3.4e38f, mn02 = 3.4e38f, mn03 = 3.4e38f;
    float mn10 = 3.4e38f, mn11 = 3.4e38f, mn12 = 3.4e38f, mn13 = 3.4e38f;

    const int tb = nrow + 2 * kq;   // in [0,13]
    uint32_t rh[6], rl[6];
    #pragma unroll
    for (int m = 0; m < 5; m++) {
        rh[m] = pair_hi[tb + 8 * m];
        rl[m] = pair_lo[tb + 8 * m];
    }
    rh[5] = 0u; rl[5] = 0u;

    #pragma unroll 1
    for (int it = 0; it < 22; it++) {
        const int t3 = it * 3;
        TILE(0, t3);
        TILE(2, t3 + 1);
        TILE(4, t3 + 2);
    }

    // ---- reduce rows in-thread, then across row groups via shfl ----
    float m0 = fminf(mn00, mn02);   // nt0, col 2kq
    float m1 = fminf(mn01, mn03);   // nt0, col 2kq+1
    float m2 = fminf(mn10, mn12);   // nt1, col 2kq
    float m3 = fminf(mn11, mn13);   // nt1, col 2kq+1
    #pragma unroll
    for (int off = 4; off < 32; off <<= 1) {
        m0 = fminf(m0, __shfl_xor_sync(0xffffffffu, m0, off));
        m1 = fminf(m1, __shfl_xor_sync(0xffffffffu, m1, off));
        m2 = fminf(m2, __shfl_xor_sync(0xffffffffu, m2, off));
        m3 = fminf(m3, __shfl_xor_sync(0xffffffffu, m3, off));
    }
    if (nrow == 0) {
        const int n0 = w * 16 + 2 * kq;
        dsh[n0]     = (m0 + ssq_sh[n0])     * (1.0f / Kc);
        dsh[n0 + 1] = (m1 + ssq_sh[n0 + 1]) * (1.0f / Kc);
        dsh[n0 + 8] = (m2 + ssq_sh[n0 + 8]) * (1.0f / Kc);
        dsh[n0 + 9] = (m3 + ssq_sh[n0 + 9]) * (1.0f / Kc);
    }
    __syncthreads();

    // ---- FC epilogue: warp 0 -> class 0, warp 1 -> class 1 ----
    if (tid < 2 * 32) {
        const int c = tid >> 5;
        const int l = tid & 31;
        float p = dsh[l] * fc_w[c * Lc + l]
                + dsh[l + 32] * fc_w[c * Lc + l + 32];
        #pragma unroll
        for (int off = 16; off > 0; off >>= 1)
            p += __shfl_down_sync(0xffffffffu, p, off);
        if (l == 0) out[b * 2 + c] = p + fc_b[c];
    }
}

extern "C" void kernel_launch(void* const* d_in, const int* in_sizes, int n_in,
                              void* d_out, int out_size)
{
    (void)in_sizes; (void)n_in; (void)out_size;
    const float* ts   = (const float*)d_in[0];
    const float* shp  = (const float*)d_in[1];
    const float* fc_w = (const float*)d_in[2];
    const float* fc_b = (const float*)d_in[3];
    float* out        = (float*)d_out;
    shapelet_bmma<<<Bc, 128>>>(ts, shp, fc_w, fc_b, out);
}